// round 6
// baseline (speedup 1.0000x reference)
#include <cuda_runtime.h>
#include <cstdint>

// QPChargeNormalization — persistent static-stride, register-resident,
// with L2 prefetch of the next row to keep DRAM busy through the
// per-row reduction bubble.
//
// Per row b (B=4096): n=8192, c=[c_iso|c_aniso], q=[int_iso|int_aniso]
//   h = (sum(charge[b]) - q.c) / (q.q),  x = c + h*q
// Output = [sol_iso (B*4096) | sol_aniso (B*4096)]

#define NT    512
#define GRID  296          // 2 CTAs/SM (register-limited)
#define NCH   256

__device__ __forceinline__ float dot4(float4 a, float4 b) {
    return fmaf(a.x, b.x, fmaf(a.y, b.y, fmaf(a.z, b.z, a.w * b.w)));
}

__device__ __forceinline__ float4 axpy4(float h, float4 q, float4 c) {
    float4 o;
    o.x = fmaf(h, q.x, c.x);
    o.y = fmaf(h, q.y, c.y);
    o.z = fmaf(h, q.z, c.z);
    o.w = fmaf(h, q.w, c.w);
    return o;
}

__device__ __forceinline__ void pf_l2(const void* p) {
    asm volatile("prefetch.global.L2 [%0];" :: "l"(p));
}

__global__ void __launch_bounds__(NT)
qp_kernel(const float4* __restrict__ c_iso,
          const float4* __restrict__ c_aniso,
          const float4* __restrict__ q_iso,
          const float4* __restrict__ q_aniso,
          const float*  __restrict__ charge,
          float4*       __restrict__ out,
          int B)
{
    const int tid  = threadIdx.x;
    const int wid  = tid >> 5;
    const int lane = tid & 31;

    __shared__ float s_p[48];          // [0..16) qc, [16..32) qq, [32..48) Q

    for (int r = blockIdx.x; r < B; r += GRID) {
        const size_t row4 = (size_t)r * 1024;

        // 8 streaming float4 demand loads straight into registers.
        float4 c0 = __ldcs(c_iso   + row4 + tid);
        float4 c1 = __ldcs(c_iso   + row4 + tid + NT);
        float4 c2 = __ldcs(c_aniso + row4 + tid);
        float4 c3 = __ldcs(c_aniso + row4 + tid + NT);
        float4 q0 = __ldcs(q_iso   + row4 + tid);
        float4 q1 = __ldcs(q_iso   + row4 + tid + NT);
        float4 q2 = __ldcs(q_aniso + row4 + tid);
        float4 q3 = __ldcs(q_aniso + row4 + tid + NT);
        float  Qv = (tid < NCH) ? __ldcs(charge + (size_t)r * NCH + tid) : 0.0f;

        // Prefetch next row into L2: each 128B line covers 8 threads' float4,
        // so threads with (tid&7)==0 prefetch all 512 lines of the 4 arrays.
        // This keeps DRAM fetching during the reduction/store phase below.
        const int rn = r + GRID;
        if (rn < B && (tid & 7) == 0) {
            const size_t nrow4 = (size_t)rn * 1024;
            pf_l2(c_iso   + nrow4 + tid);
            pf_l2(c_iso   + nrow4 + tid + NT);
            pf_l2(c_aniso + nrow4 + tid);
            pf_l2(c_aniso + nrow4 + tid + NT);
            pf_l2(q_iso   + nrow4 + tid);
            pf_l2(q_iso   + nrow4 + tid + NT);
            pf_l2(q_aniso + nrow4 + tid);
            pf_l2(q_aniso + nrow4 + tid + NT);
            if (tid < 8 * 32)   // first 8 of the prefetching threads: charge lines
                pf_l2(charge + (size_t)rn * NCH + (tid >> 5) * 32);
        }

        float qc = dot4(q0, c0) + dot4(q1, c1) + dot4(q2, c2) + dot4(q3, c3);
        float qq = dot4(q0, q0) + dot4(q1, q1) + dot4(q2, q2) + dot4(q3, q3);

        #pragma unroll
        for (int m = 16; m; m >>= 1) {
            qc += __shfl_xor_sync(0xffffffffu, qc, m);
            qq += __shfl_xor_sync(0xffffffffu, qq, m);
            Qv += __shfl_xor_sync(0xffffffffu, Qv, m);
        }
        if (lane == 0) { s_p[wid] = qc; s_p[16 + wid] = qq; s_p[32 + wid] = Qv; }
        __syncthreads();   // the only barrier per row

        // Every warp redundantly reduces the 16 partials — no second barrier.
        float a  = (lane < 16) ? s_p[lane]      : 0.0f;
        float g  = (lane < 16) ? s_p[16 + lane] : 0.0f;
        float qs = (lane < 16) ? s_p[32 + lane] : 0.0f;
        #pragma unroll
        for (int m = 8; m; m >>= 1) {
            a  += __shfl_xor_sync(0xffffffffu, a,  m);
            g  += __shfl_xor_sync(0xffffffffu, g,  m);
            qs += __shfl_xor_sync(0xffffffffu, qs, m);
        }
        const float h = __shfl_sync(0xffffffffu, (qs - a) / g, 0);

        float4* oi = out + row4;                        // iso block
        float4* oa = out + (size_t)B * 1024 + row4;     // aniso block
        __stcs(oi + tid,      axpy4(h, q0, c0));
        __stcs(oi + tid + NT, axpy4(h, q1, c1));
        __stcs(oa + tid,      axpy4(h, q2, c2));
        __stcs(oa + tid + NT, axpy4(h, q3, c3));

        __syncthreads();   // keep warps in lockstep so s_p reuse is safe
    }
}

extern "C" void kernel_launch(void* const* d_in, const int* in_sizes, int n_in,
                              void* d_out, int out_size)
{
    const float4* c_iso   = (const float4*)d_in[0];
    const float4* c_aniso = (const float4*)d_in[1];
    const float4* q_iso   = (const float4*)d_in[2];
    const float4* q_aniso = (const float4*)d_in[3];
    const float*  charge  = (const float*) d_in[4];
    float4*       out     = (float4*)d_out;

    const int B = in_sizes[4] / NCH;   // charge is [B, 256]

    qp_kernel<<<GRID, NT>>>(c_iso, c_aniso, q_iso, q_aniso, charge, out, B);
}

// round 8
// speedup vs baseline: 1.0664x; 1.0664x over previous
#include <cuda_runtime.h>
#include <cstdint>

// QPChargeNormalization — two-pass, low-register, 3 CTAs/SM.
// Per row b (B=4096): n=8192, c=[c_iso|c_aniso], q=[int_iso|int_aniso]
//   h = (sum(charge[b]) - q.c) / (q.q),  x = c + h*q
// Output = [sol_iso (B*4096) | sol_aniso (B*4096)]
//
// Pass 1 streams c,q through transient registers to form (q.c, q.q);
// pass 2 re-reads the row (L2-resident by then) for the axpy+store.
// Halving register residency lifts occupancy from 2 to 3 CTAs/SM so the
// per-row reduction bubble is covered by co-resident CTAs.

#define NT   512
#define NCH  256

__device__ __forceinline__ float dot4(float4 a, float4 b) {
    return fmaf(a.x, b.x, fmaf(a.y, b.y, fmaf(a.z, b.z, a.w * b.w)));
}

__device__ __forceinline__ float4 axpy4(float h, float4 q, float4 c) {
    float4 o;
    o.x = fmaf(h, q.x, c.x);
    o.y = fmaf(h, q.y, c.y);
    o.z = fmaf(h, q.z, c.z);
    o.w = fmaf(h, q.w, c.w);
    return o;
}

__global__ void __launch_bounds__(NT, 3)
qp_kernel(const float4* __restrict__ c_iso,
          const float4* __restrict__ c_aniso,
          const float4* __restrict__ q_iso,
          const float4* __restrict__ q_aniso,
          const float*  __restrict__ charge,
          float4*       __restrict__ out,
          int B)
{
    const int tid  = threadIdx.x;
    const int wid  = tid >> 5;
    const int lane = tid & 31;
    const int r    = blockIdx.x;
    const size_t row4 = (size_t)r * 1024;

    const float4* ci = c_iso   + row4;
    const float4* ca = c_aniso + row4;
    const float4* qi = q_iso   + row4;
    const float4* qa = q_aniso + row4;

    __shared__ float s_p[48];          // [0..16) qc, [16..32) qq, [32..48) Q

    // ---- pass 1: transient loads -> dot accumulators (low reg pressure) ----
    float4 a0 = __ldcg(ci + tid);
    float4 b0 = __ldcg(qi + tid);
    float4 a1 = __ldcg(ci + tid + NT);
    float4 b1 = __ldcg(qi + tid + NT);
    float  Qv = (tid < NCH) ? __ldcg(charge + (size_t)r * NCH + tid) : 0.0f;

    float qc = dot4(b0, a0) + dot4(b1, a1);
    float qq = dot4(b0, b0) + dot4(b1, b1);

    a0 = __ldcg(ca + tid);
    b0 = __ldcg(qa + tid);
    a1 = __ldcg(ca + tid + NT);
    b1 = __ldcg(qa + tid + NT);

    qc += dot4(b0, a0) + dot4(b1, a1);
    qq += dot4(b0, b0) + dot4(b1, b1);

    // ---- reduction: warp butterfly -> smem partials -> one barrier ----
    #pragma unroll
    for (int m = 16; m; m >>= 1) {
        qc += __shfl_xor_sync(0xffffffffu, qc, m);
        qq += __shfl_xor_sync(0xffffffffu, qq, m);
        Qv += __shfl_xor_sync(0xffffffffu, Qv, m);
    }
    if (lane == 0) { s_p[wid] = qc; s_p[16 + wid] = qq; s_p[32 + wid] = Qv; }
    __syncthreads();

    // Every warp redundantly reduces the 16 partials — no second barrier.
    float sa = (lane < 16) ? s_p[lane]      : 0.0f;
    float sg = (lane < 16) ? s_p[16 + lane] : 0.0f;
    float sq = (lane < 16) ? s_p[32 + lane] : 0.0f;
    #pragma unroll
    for (int m = 8; m; m >>= 1) {
        sa += __shfl_xor_sync(0xffffffffu, sa, m);
        sg += __shfl_xor_sync(0xffffffffu, sg, m);
        sq += __shfl_xor_sync(0xffffffffu, sq, m);
    }
    const float h = __shfl_sync(0xffffffffu, (sq - sa) / sg, 0);

    // ---- pass 2: re-read (L2 hits) + axpy + streaming store ----
    float4* oi = out + row4;                        // iso block
    float4* oa = out + (size_t)B * 1024 + row4;     // aniso block

    a0 = __ldcg(ci + tid);
    b0 = __ldcg(qi + tid);
    a1 = __ldcg(ci + tid + NT);
    b1 = __ldcg(qi + tid + NT);
    __stcs(oi + tid,      axpy4(h, b0, a0));
    __stcs(oi + tid + NT, axpy4(h, b1, a1));

    a0 = __ldcg(ca + tid);
    b0 = __ldcg(qa + tid);
    a1 = __ldcg(ca + tid + NT);
    b1 = __ldcg(qa + tid + NT);
    __stcs(oa + tid,      axpy4(h, b0, a0));
    __stcs(oa + tid + NT, axpy4(h, b1, a1));
}

extern "C" void kernel_launch(void* const* d_in, const int* in_sizes, int n_in,
                              void* d_out, int out_size)
{
    const float4* c_iso   = (const float4*)d_in[0];
    const float4* c_aniso = (const float4*)d_in[1];
    const float4* q_iso   = (const float4*)d_in[2];
    const float4* q_aniso = (const float4*)d_in[3];
    const float*  charge  = (const float*) d_in[4];
    float4*       out     = (float4*)d_out;

    const int B = in_sizes[4] / NCH;   // charge is [B, 256]

    qp_kernel<<<B, NT>>>(c_iso, c_aniso, q_iso, q_aniso, charge, out, B);
}